// round 3
// baseline (speedup 1.0000x reference)
#include <cuda_runtime.h>

// ---------------------------------------------------------------------------
// Fused: channel-mix (64->16) -> double-unfold 3x3 along W (masked) ->
//        group conv mix (8g x 9taps -> 32) -> roll(+1,H) -> NCHW out.
// One CTA per batch image; T4 intermediate in shared memory; all hot math in
// packed fma.rn.f32x2 (128 FMA/cyc/SM on sm_103a).
// ---------------------------------------------------------------------------

typedef unsigned long long ull;

#define ROWP 20                    // padded floats per (g,h,wd) row (bank-perm)
#define WPAD 18                    // wd entries per (g,h): w+2 for w in [-2,15]
#define T4N   (8*14*WPAD*ROWP)     // 40320 floats
#define WEFFN (5*8*5*32)           // 6400 floats
#define WMIXN 1024                 // 64x16
#define SMEM_FLOATS (T4N + WEFFN + WMIXN)

__device__ __forceinline__ ull pack2(float lo, float hi){
    ull r; asm("mov.b64 %0, {%1, %2};" : "=l"(r) : "f"(lo), "f"(hi)); return r;
}
__device__ __forceinline__ void unpack2(ull v, float &lo, float &hi){
    asm("mov.b64 {%0, %1}, %2;" : "=f"(lo), "=f"(hi) : "l"(v));
}
__device__ __forceinline__ void ffma2(ull &d, ull a, ull b){
    asm("fma.rn.f32x2 %0, %1, %2, %0;" : "+l"(d) : "l"(a), "l"(b));
}

__global__ void __launch_bounds__(512, 1)
fused_mix_unfold_conv(const float* __restrict__ x,
                      const float* __restrict__ wconv,
                      const float* __restrict__ wmix,
                      float* __restrict__ out)
{
    extern __shared__ float smem[];
    float* t4s   = smem;                 // [g][h][wd(18)][ROWP]
    float* weffs = smem + T4N;           // [cls(5)][g(8)][d(5)][j(32)]
    float* wmixs = weffs + WEFFN;        // [j(64)][i(16)]

    const int tid = threadIdx.x;
    const int b   = blockIdx.x;

    // ---------------- stage 0: wmix copy + pad-zero + Weff ----------------
    for (int i = tid; i < WMIXN; i += 512) wmixs[i] = wmix[i];

    // zero T4 pad rows: wd in {0,1,16,17}
    for (int i = tid; i < 8*14*4*ROWP; i += 512) {
        int row = i / ROWP, p = i % ROWP;
        int g = row / 56, rr = row % 56;
        int h = rr / 4,  wi = rr % 4;
        int wd = (wi < 2) ? wi : (wi + 14);
        t4s[((g*14 + h)*WPAD + wd)*ROWP + p] = 0.f;
    }

    // Weff[cls][g][d][j]: collapse (k1,k2) double-unfold with both masks.
    // cls representative w: 0,1,12,13, interior(5).
    for (int e = tid; e < WEFFN; e += 512) {
        int j   = e & 31;
        int d   = (e >> 5) % 5;
        int g   = (e / 160) % 8;
        int cls = e / 1280;
        int w   = (cls==0)?0 : (cls==1)?1 : (cls==2)?12 : (cls==3)?13 : 5;
        float a = 0.f;
        int s = w + d - 2;                 // source column of t4
        if (s >= 0 && s <= 13) {
            for (int k2 = 0; k2 < 3; ++k2) {
                int k1 = d - k2;
                if (k1 < 0 || k1 > 2) continue;
                int hm = w + k2 - 1;       // intermediate-unfold position
                if (hm < 0 || hm > 13) continue;
                a += wconv[((g*3 + k2)*3 + k1)*32 + j];
            }
        }
        weffs[e] = a;
    }
    __syncthreads();

    // ---------------- stage 1: T4[g,h,w,p] = sum_j x[b,j,g,h,w]*wmix[j,p] --
    if (tid < 392) {                       // 392*4 = 1568 spatial-group points
        const float* xb = x + (size_t)b * 100352 + tid * 4;
        ull acc[4][8];
        #pragma unroll
        for (int pt = 0; pt < 4; ++pt)
            #pragma unroll
            for (int pp = 0; pp < 8; ++pp) acc[pt][pp] = 0ull;

        #pragma unroll 4
        for (int j = 0; j < 64; ++j) {
            float4 xv = *(const float4*)(xb + j * 1568);   // 4 consecutive points
            const ulonglong2* wrow = (const ulonglong2*)(wmixs + j * 16);
            ulonglong2 w01 = wrow[0], w23 = wrow[1], w45 = wrow[2], w67 = wrow[3];
            ull wp[8] = {w01.x, w01.y, w23.x, w23.y, w45.x, w45.y, w67.x, w67.y};
            ull xbc[4] = {pack2(xv.x, xv.x), pack2(xv.y, xv.y),
                          pack2(xv.z, xv.z), pack2(xv.w, xv.w)};
            #pragma unroll
            for (int pt = 0; pt < 4; ++pt)
                #pragma unroll
                for (int pp = 0; pp < 8; ++pp)
                    ffma2(acc[pt][pp], xbc[pt], wp[pp]);
        }
        #pragma unroll
        for (int pt = 0; pt < 4; ++pt) {
            int s = tid * 4 + pt;
            int g = s / 196, rem = s % 196;
            int h = rem / 14, w = rem % 14;
            float* dst = &t4s[((g*14 + h)*WPAD + (w + 2))*ROWP];
            #pragma unroll
            for (int q = 0; q < 4; ++q) {
                float a0,a1,a2,a3;
                unpack2(acc[pt][2*q],   a0, a1);
                unpack2(acc[pt][2*q+1], a2, a3);
                *(float4*)(dst + 4*q) = make_float4(a0, a1, a2, a3);
            }
        }
    }
    __syncthreads();

    // ---------------- stage 2: out[b, j*16+p, (h+1)%14, w] ----------------
    // task = (h*14 + w)*8 + jg; each task does 4 j (jg*4..+3) x 16 p.
    const size_t obase = (size_t)b * 512 * 196;
    #pragma unroll 1
    for (int it = 0; it < 4; ++it) {
        int task = tid + it * 512;
        if (task >= 1568) break;
        int jg = task & 7;
        int wv = (task >> 3) % 14;
        int h  = task / 112;
        int cls = (wv==0)?0 : (wv==1)?1 : (wv==12)?2 : (wv==13)?3 : 4;

        ull acc[4][8];
        #pragma unroll
        for (int a = 0; a < 4; ++a)
            #pragma unroll
            for (int p = 0; p < 8; ++p) acc[a][p] = 0ull;

        #pragma unroll 1
        for (int g = 0; g < 8; ++g) {
            const float* wg  = weffs + ((cls*8 + g)*5)*32 + jg*4;
            const float* tgh = t4s + ((g*14 + h)*WPAD + wv)*ROWP; // wd = wv+d
            #pragma unroll
            for (int d = 0; d < 5; ++d) {
                float4 wf = *(const float4*)(wg + d*32);
                const ulonglong2* tp = (const ulonglong2*)(tgh + d*ROWP);
                ulonglong2 t01 = tp[0], t23 = tp[1], t45 = tp[2], t67 = tp[3];
                ull tq[8] = {t01.x, t01.y, t23.x, t23.y,
                             t45.x, t45.y, t67.x, t67.y};
                ull w0 = pack2(wf.x, wf.x), w1 = pack2(wf.y, wf.y);
                ull w2 = pack2(wf.z, wf.z), w3 = pack2(wf.w, wf.w);
                #pragma unroll
                for (int pp = 0; pp < 8; ++pp) {
                    ffma2(acc[0][pp], tq[pp], w0);
                    ffma2(acc[1][pp], tq[pp], w1);
                    ffma2(acc[2][pp], tq[pp], w2);
                    ffma2(acc[3][pp], tq[pp], w3);
                }
            }
        }

        int h_o = h + 1; if (h_o == 14) h_o = 0;     // roll(+1, H)
        float* ob = out + obase + h_o*14 + wv;
        #pragma unroll
        for (int jp = 0; jp < 4; ++jp) {
            int cbase = (jg*4 + jp)*16;
            #pragma unroll
            for (int pp = 0; pp < 8; ++pp) {
                float lo, hi;
                unpack2(acc[jp][pp], lo, hi);
                ob[(size_t)(cbase + 2*pp    ) * 196] = lo;
                ob[(size_t)(cbase + 2*pp + 1) * 196] = hi;
            }
        }
    }
}

extern "C" void kernel_launch(void* const* d_in, const int* in_sizes, int n_in,
                              void* d_out, int out_size) {
    const float* x     = (const float*)d_in[0];
    const float* wconv = (const float*)d_in[1];
    const float* wmix  = (const float*)d_in[2];
    float* out = (float*)d_out;
    (void)in_sizes; (void)n_in; (void)out_size;

    size_t smem_bytes = (size_t)SMEM_FLOATS * sizeof(float);   // 190,976 B
    cudaFuncSetAttribute(fused_mix_unfold_conv,
                         cudaFuncAttributeMaxDynamicSharedMemorySize,
                         (int)smem_bytes);
    fused_mix_unfold_conv<<<128, 512, smem_bytes>>>(x, wconv, wmix, out);
}

// round 4
// speedup vs baseline: 1.8431x; 1.8431x over previous
#include <cuda_runtime.h>

// ---------------------------------------------------------------------------
// Fused: channel-mix (64->16) -> double-unfold 3x3 along W (masked) ->
//        group conv mix (8g x 9taps -> 32) -> roll(+1,H) -> NCHW out.
//
// One CTA per batch image (grid=128, 512 threads).
// Stage 1 writes T4 transposed (p-major rows of 18 wd floats) to smem.
// Stage 2: lane=(p,jg), w-packed f32x2 accumulators, interior 5-tap weights
// + rank-1 edge corrections at w=0/w=13. All hot math fma.rn.f32x2.
// ---------------------------------------------------------------------------

typedef unsigned long long ull;

#define ROWBLK 290                    // floats per (g,h) block: 16*18 + 2 pad
#define T4N    (8*14*ROWBLK)          // 32480 floats
#define WEFFN  (8*5*32)               // 1280 floats
#define WMIXN  1024                   // 64*16
#define CORRN  (8*32)                 // ulls per correction table
// byte layout: t4s | weffs | wmixs | corr0d | corr13d
#define SMEM_BYTES (T4N*4 + WEFFN*4 + WMIXN*4 + CORRN*8*2)   // 143232

__device__ __forceinline__ ull pack2(float lo, float hi){
    ull r; asm("mov.b64 %0, {%1, %2};" : "=l"(r) : "f"(lo), "f"(hi)); return r;
}
__device__ __forceinline__ void unpack2(ull v, float &lo, float &hi){
    asm("mov.b64 {%0, %1}, %2;" : "=f"(lo), "=f"(hi) : "l"(v));
}
__device__ __forceinline__ void ffma2(ull &d, ull a, ull b){
    asm("fma.rn.f32x2 %0, %1, %2, %0;" : "+l"(d) : "l"(a), "l"(b));
}

__global__ void __launch_bounds__(512, 1)
fused_mix_unfold_conv(const float* __restrict__ x,
                      const float* __restrict__ wconv,
                      const float* __restrict__ wmix,
                      float* __restrict__ out)
{
    extern __shared__ float smem[];
    float* t4s     = smem;                       // [g][h] blocks of ROWBLK
    float* weffs   = smem + T4N;                 // [g][d][32 j]
    float* wmixs   = weffs + WEFFN;              // [j64][p16]
    ull*   corr0d  = (ull*)(wmixs + WMIXN);      // [g][32 j]  (-c, 0)
    ull*   corr13d = corr0d + CORRN;             // [g][32 j]  (0, -c)

    const int tid = threadIdx.x;
    const int b   = blockIdx.x;

    // ---------------- prologue: wmix copy, T4 pad-zero, Weff, corrections --
    for (int i = tid; i < WMIXN; i += 512) wmixs[i] = wmix[i];

    // zero pad wd rows {0,1,16,17} for all (g,h,p)
    for (int i = tid; i < 8*14*16*4; i += 512) {
        int blk = i >> 6, r = i & 63;
        int p = r >> 2, wi = r & 3;
        int wd = (wi < 2) ? wi : (wi + 14);
        t4s[blk*ROWBLK + p*18 + wd] = 0.f;
    }

    // interior Weff[g][d][j] = sum_{kb, ka=d-kb in [0,2]} wconv[g][kb][ka][j]
    for (int e = tid; e < WEFFN; e += 512) {
        int j = e & 31;
        int d = (e >> 5) % 5;
        int g = e / 160;
        float a = 0.f;
        #pragma unroll
        for (int kb = 0; kb < 3; ++kb) {
            int ka = d - kb;
            if (ka >= 0 && ka <= 2)
                a += wconv[((g*3 + kb)*3 + ka)*32 + j];
        }
        weffs[e] = a;
    }

    // corrections: w=0 drops kb=0 (only ka=2 survives pad): c0 = wconv[g][0][2][j]
    //              w=13 drops kb=2 (only ka=0 survives):     c13 = wconv[g][2][0][j]
    for (int e = tid; e < CORRN; e += 512) {
        int j = e & 31, g = e >> 5;
        corr0d [e] = pack2(-wconv[((g*3 + 0)*3 + 2)*32 + j], 0.f);
        corr13d[e] = pack2(0.f, -wconv[((g*3 + 2)*3 + 0)*32 + j]);
    }
    __syncthreads();

    // ---------------- stage 1: T4[g,h,w,p] = sum_j x[b,j,s] * wmix[j,p] ----
    if (tid < 392) {
        const float* xb = x + (size_t)b * 100352 + tid * 4;
        ull acc[4][8];
        #pragma unroll
        for (int pt = 0; pt < 4; ++pt)
            #pragma unroll
            for (int pp = 0; pp < 8; ++pp) acc[pt][pp] = 0ull;

        #pragma unroll 8
        for (int j = 0; j < 64; ++j) {
            float4 xv = *(const float4*)(xb + j * 1568);
            const ulonglong2* wrow = (const ulonglong2*)(wmixs + j * 16);
            ulonglong2 w01 = wrow[0], w23 = wrow[1], w45 = wrow[2], w67 = wrow[3];
            ull wp[8] = {w01.x, w01.y, w23.x, w23.y, w45.x, w45.y, w67.x, w67.y};
            ull xbc[4] = {pack2(xv.x, xv.x), pack2(xv.y, xv.y),
                          pack2(xv.z, xv.z), pack2(xv.w, xv.w)};
            #pragma unroll
            for (int pt = 0; pt < 4; ++pt)
                #pragma unroll
                for (int pp = 0; pp < 8; ++pp)
                    ffma2(acc[pt][pp], xbc[pt], wp[pp]);
        }
        #pragma unroll
        for (int pt = 0; pt < 4; ++pt) {
            int s = tid * 4 + pt;
            int g = s / 196, rem = s % 196;
            int h = rem / 14, w = rem % 14;
            float* dst = t4s + (g*14 + h)*ROWBLK + (w + 2);
            float v[16];
            #pragma unroll
            for (int q = 0; q < 8; ++q) unpack2(acc[pt][q], v[2*q], v[2*q+1]);
            #pragma unroll
            for (int p = 0; p < 16; ++p) dst[p*18] = v[p];
        }
    }
    __syncthreads();

    // ---------------- stage 2 ---------------------------------------------
    const int lid = tid & 31;
    const int wid = tid >> 5;
    const int p   = lid & 15;
    const int jg  = lid >> 4;               // 0..1

    const size_t obase = (size_t)b * 100352;

    #pragma unroll 1
    for (int it = 0; it < 4; ++it) {
        int task = wid + 16*it;             // SMSP-balanced
        if (task >= 56) continue;
        int jq = task & 3;
        int h  = task >> 2;
        int jb = jq*8 + jg*4;               // this thread's 4 j's: jb..jb+3

        ull a0[7], a1[7], a2[7], a3[7];
        #pragma unroll
        for (int k = 0; k < 7; ++k) { a0[k]=0; a1[k]=0; a2[k]=0; a3[k]=0; }

        #pragma unroll 1
        for (int g = 0; g < 8; ++g) {
            const float2* row = (const float2*)(t4s + (g*14 + h)*ROWBLK + p*18);
            float2 f[9];
            #pragma unroll
            for (int k = 0; k < 9; ++k) f[k] = row[k];

            ull E[9], O[8];
            #pragma unroll
            for (int k = 0; k < 9; ++k) E[k] = pack2(f[k].x, f[k].y);
            #pragma unroll
            for (int k = 0; k < 8; ++k) O[k] = pack2(f[k].y, f[k+1].x);

            const float* wg = weffs + g*5*32 + jb;
            #pragma unroll
            for (int d = 0; d < 5; ++d) {
                float4 wv = *(const float4*)(wg + d*32);
                ull w0 = pack2(wv.x, wv.x), w1 = pack2(wv.y, wv.y);
                ull w2 = pack2(wv.z, wv.z), w3 = pack2(wv.w, wv.w);
                #pragma unroll
                for (int wp = 0; wp < 7; ++wp) {
                    ull t = (d & 1) ? O[((d-1)>>1) + wp] : E[(d>>1) + wp];
                    ffma2(a0[wp], t, w0);
                    ffma2(a1[wp], t, w1);
                    ffma2(a2[wp], t, w2);
                    ffma2(a3[wp], t, w3);
                }
            }
            // edge corrections: w=0 uses t4 float idx2 (f[1].x), lo half of wp0
            //                   w=13 uses idx15 (f[7].y), hi half of wp6
            {
                const ulonglong2* c0 = (const ulonglong2*)(corr0d  + g*32 + jb);
                const ulonglong2* c3 = (const ulonglong2*)(corr13d + g*32 + jb);
                ulonglong2 c0a = c0[0], c0b = c0[1];
                ulonglong2 c3a = c3[0], c3b = c3[1];
                ull m2  = pack2(f[1].x, f[1].x);
                ull m15 = pack2(f[7].y, f[7].y);
                ffma2(a0[0], m2, c0a.x);  ffma2(a1[0], m2, c0a.y);
                ffma2(a2[0], m2, c0b.x);  ffma2(a3[0], m2, c0b.y);
                ffma2(a0[6], m15, c3a.x); ffma2(a1[6], m15, c3a.y);
                ffma2(a2[6], m15, c3b.x); ffma2(a3[6], m15, c3b.y);
            }
        }

        int h_o = h + 1; if (h_o == 14) h_o = 0;   // roll(+1, H)

        #pragma unroll
        for (int jj = 0; jj < 4; ++jj) {
            ull* a = (jj==0) ? a0 : (jj==1) ? a1 : (jj==2) ? a2 : a3;
            int ch = (jb + jj)*16 + p;
            float* ob = out + obase + (size_t)ch*196 + h_o*14;
            if ((h_o & 1) == 0) {
                ((ulonglong2*)ob)[0]     = make_ulonglong2(a[0], a[1]);
                ((ulonglong2*)(ob+4))[0] = make_ulonglong2(a[2], a[3]);
                ((ulonglong2*)(ob+8))[0] = make_ulonglong2(a[4], a[5]);
                *(ull*)(ob+12) = a[6];
            } else {
                *(ull*)ob = a[0];
                ((ulonglong2*)(ob+2))[0]  = make_ulonglong2(a[1], a[2]);
                ((ulonglong2*)(ob+6))[0]  = make_ulonglong2(a[3], a[4]);
                ((ulonglong2*)(ob+10))[0] = make_ulonglong2(a[5], a[6]);
            }
        }
    }
}

extern "C" void kernel_launch(void* const* d_in, const int* in_sizes, int n_in,
                              void* d_out, int out_size) {
    const float* x     = (const float*)d_in[0];
    const float* wconv = (const float*)d_in[1];
    const float* wmix  = (const float*)d_in[2];
    float* out = (float*)d_out;
    (void)in_sizes; (void)n_in; (void)out_size;

    cudaFuncSetAttribute(fused_mix_unfold_conv,
                         cudaFuncAttributeMaxDynamicSharedMemorySize,
                         SMEM_BYTES);
    fused_mix_unfold_conv<<<128, 512, SMEM_BYTES>>>(x, wconv, wmix, out);
}